// round 15
// baseline (speedup 1.0000x reference)
#include <cuda_runtime.h>
#include <cuda_fp16.h>
#include <cstdint>

// ChunkStickyRouter on GB300 (sm_103a) — fp16 mma.sync GEMM1, barrier every 2nd
// k-chunk, A-prefetch distance 2 (dual register sets), fused x-cvt, last-CTA
// logits, per-chunk scan+fill. B=8, S=4096, D=2048, H=1024, E=8, CHUNK=128, TAU=0.7

#define B_  8
#define S_  4096
#define D_  2048
#define H_  1024
#define E_  8
#define CHUNK_ 128
#define NCHUNK_ 256
#define TAU_ 0.7f

// GEMM1 tiling
#define BM_ 128
#define BN_ 128
#define BK_ 32
#define NKC_ (D_ / BK_)        // 64
#define NTHR_ 256
#define ROWB_ 80               // smem row stride (bytes): conflict-free LDSM
#define TILE_ (128 * ROWB_)            // 10240 B per fp16 tile
#define NA_ 4                          // A stages
#define NB_ 5                          // B stages
#define BOFF_ (NA_ * TILE_)            // 40960
#define SM_B1_   (BOFF_ + NB_ * TILE_) // 92160
#define SM_PART_ (SM_B1_ + 512)
#define SMEM_TOTAL_ (SM_PART_ + 1024)  // 93696  -> 2 CTAs/SM

__device__ __half g_w1t[(size_t)H_ * D_];         // W1^T as fp16, [n][k]
__device__ float  g_hsum[NCHUNK_ * H_];
__device__ float  g_clogits[NCHUNK_ * E_];
__device__ int    g_cnt[NCHUNK_];                 // per-chunk completion counters

// ---------------- PTX helpers ----------------
__device__ __forceinline__ uint32_t smem_to_u32(const void* p) {
    uint32_t a;
    asm("{ .reg .u64 t; cvta.to.shared.u64 t, %1; cvt.u32.u64 %0, t; }" : "=r"(a) : "l"(p));
    return a;
}
__device__ __forceinline__ uint32_t pack_half2(float x, float y) {
    uint32_t u;
    asm("cvt.rn.f16x2.f32 %0, %1, %2;" : "=r"(u) : "f"(y), "f"(x));
    return u;
}
#define CP_ASYNC16(dst, src) \
    asm volatile("cp.async.cg.shared.global [%0], [%1], 16;" :: "r"(dst), "l"(src))
#define CP_COMMIT() asm volatile("cp.async.commit_group;" ::: "memory")
#define CP_WAITG1() asm volatile("cp.async.wait_group 1;" ::: "memory")

#define LDSM4(r, a) \
    asm volatile("ldmatrix.sync.aligned.m8n8.x4.shared.b16 {%0,%1,%2,%3}, [%4];" \
        : "=r"((r)[0]), "=r"((r)[1]), "=r"((r)[2]), "=r"((r)[3]) : "r"(a))
#define LDSM2(r, a) \
    asm volatile("ldmatrix.sync.aligned.m8n8.x2.shared.b16 {%0,%1}, [%2];" \
        : "=r"((r)[0]), "=r"((r)[1]) : "r"(a))

#define MMA_F32(d, a, b) \
    asm volatile("mma.sync.aligned.m16n8k16.row.col.f32.f16.f16.f32 " \
        "{%0,%1,%2,%3}, {%4,%5,%6,%7}, {%8,%9}, {%0,%1,%2,%3};" \
        : "+f"((d)[0]), "+f"((d)[1]), "+f"((d)[2]), "+f"((d)[3]) \
        : "r"((a)[0]), "r"((a)[1]), "r"((a)[2]), "r"((a)[3]), "r"((b)[0]), "r"((b)[1]))

#define STS64(addr, v0, v1) \
    asm volatile("st.shared.v2.b32 [%0], {%1, %2};" :: "r"(addr), "r"(v0), "r"(v1))

// ---------------- prepass: W1 [k][n] fp32 -> W1^T [n][k] fp16, 64x64 tiles ----------------
__global__ __launch_bounds__(256)
void cvt_w1(const float* __restrict__ W1) {
    __shared__ float t[64][65];
    const int n0 = blockIdx.x * 64, k0 = blockIdx.y * 64;
    const int tid = threadIdx.x;

    // load 64x64 fp32 tile: thread -> (k row = tid>>4 (+16/pass), 4 n cols)
    const int kr = tid >> 4, c4 = (tid & 15) * 4;
    #pragma unroll
    for (int p = 0; p < 4; p++) {
        float4 v = *(const float4*)&W1[(size_t)(k0 + kr + p * 16) * H_ + n0 + c4];
        t[kr + p * 16][c4 + 0] = v.x;
        t[kr + p * 16][c4 + 1] = v.y;
        t[kr + p * 16][c4 + 2] = v.z;
        t[kr + p * 16][c4 + 3] = v.w;
    }
    __syncthreads();

    // store transposed: thread -> (n = tid>>2, 16 consecutive k) as 2x uint4
    const int n = tid >> 2, k16 = (tid & 3) * 16;
    uint4 h0, h1;
    h0.x = pack_half2(t[k16 + 0][n],  t[k16 + 1][n]);
    h0.y = pack_half2(t[k16 + 2][n],  t[k16 + 3][n]);
    h0.z = pack_half2(t[k16 + 4][n],  t[k16 + 5][n]);
    h0.w = pack_half2(t[k16 + 6][n],  t[k16 + 7][n]);
    h1.x = pack_half2(t[k16 + 8][n],  t[k16 + 9][n]);
    h1.y = pack_half2(t[k16 + 10][n], t[k16 + 11][n]);
    h1.z = pack_half2(t[k16 + 12][n], t[k16 + 13][n]);
    h1.w = pack_half2(t[k16 + 14][n], t[k16 + 15][n]);
    __half* dst = &g_w1t[(size_t)(n0 + n) * D_ + k0 + k16];
    *(uint4*)dst = h0;
    *(uint4*)(dst + 8) = h1;
}

// ---------------- GEMM1: relu(x@W1+b1), chunk column-sum, last-CTA logits ----------------
__global__ __launch_bounds__(NTHR_, 2)
void gemm1_mma(const float* __restrict__ x, const float* __restrict__ b1,
               const float* __restrict__ W2, const float* __restrict__ b2) {
    extern __shared__ __align__(1024) char smem[];
    const uint32_t sb = smem_to_u32(smem);
    const int tid = threadIdx.x;
    const int lane = tid & 31, wid = tid >> 5;      // 8 warps
    const int wm = wid & 1, wn = wid >> 1;          // 2(m) x 4(n), warp tile 64x32
    const int n0 = blockIdx.x * BN_;
    const int chunk = blockIdx.y;
    const int m0 = chunk * BM_;

    if (tid < BN_) ((float*)(smem + SM_B1_))[tid] = b1[n0 + tid];

    // ---- A (x fp32, LDG prefetch): thread covers 4 float4 chunks ----
    const int a_row0 = tid >> 3;            // +32*j
    const int a_k4   = tid & 7;
    const float* srcA0 = x + (size_t)(m0 + a_row0) * D_ + a_k4 * 4;
    const uint32_t dstA0 = sb + a_row0 * ROWB_ + a_k4 * 8;   // fp16: 8B per float4

    // ---- B (w1t fp16, cp.async): 2 chunks of 16B per thread ----
    const char* srcB[2]; uint32_t dstB[2];
    #pragma unroll
    for (int j = 0; j < 2; j++) {
        int q = tid + j * NTHR_;               // 0..511
        int row = q >> 2, k16 = q & 3;
        srcB[j] = (const char*)(g_w1t + (size_t)(n0 + row) * D_ + k16 * 8);
        dstB[j] = sb + BOFF_ + row * ROWB_ + k16 * 16;
    }

    const uint32_t a_off = (uint32_t)((wm * 64 + (lane & 15)) * ROWB_ + (lane >> 4) * 16);
    const uint32_t b_off = (uint32_t)(BOFF_ + (wn * 32 + (lane & 7)) * ROWB_ + ((lane >> 3) & 1) * 16);

    float acc[4][4][4];
    #pragma unroll
    for (int a = 0; a < 4; a++)
        #pragma unroll
        for (int b = 0; b < 4; b++)
            #pragma unroll
            for (int c = 0; c < 4; c++) acc[a][b][c] = 0.f;

    float4 areg0[4], areg1[4];   // dual prefetch sets (distance 2)

    // ---- prologue ----
    // A0, A1: load + convert + STS directly
    #pragma unroll
    for (int s = 0; s < 2; s++) {
        #pragma unroll
        for (int j = 0; j < 4; j++)
            areg0[j] = *(const float4*)(srcA0 + (size_t)(32 * j) * D_ + s * BK_);
        #pragma unroll
        for (int j = 0; j < 4; j++) {
            uint32_t h0 = pack_half2(areg0[j].x, areg0[j].y);
            uint32_t h1 = pack_half2(areg0[j].z, areg0[j].w);
            STS64(dstA0 + s * TILE_ + j * (32 * ROWB_), h0, h1);
        }
    }
    // A2 -> areg0, A3 -> areg1
    #pragma unroll
    for (int j = 0; j < 4; j++)
        areg0[j] = *(const float4*)(srcA0 + (size_t)(32 * j) * D_ + 2 * BK_);
    #pragma unroll
    for (int j = 0; j < 4; j++)
        areg1[j] = *(const float4*)(srcA0 + (size_t)(32 * j) * D_ + 3 * BK_);
    // B0, B1, B2 via cp.async
    #pragma unroll
    for (int s = 0; s < 3; s++) {
        #pragma unroll
        for (int j = 0; j < 2; j++)
            CP_ASYNC16(dstB[j] + s * TILE_, srcB[j] + s * 64);
        CP_COMMIT();
    }

    int bufA = 0, bufB = 0;                 // ck % 4, ck % 5
    for (int ck = 0; ck < NKC_; ck += 2) {
        CP_WAITG1();
        __syncthreads();

        // ===== even sub-iter (ck): STS A(ck+2) from areg0; LDG A(ck+4) -> areg0 =====
        if (ck + 2 < NKC_) {
            int nb = bufA + 2; if (nb >= NA_) nb -= NA_;
            uint32_t ab = dstA0 + nb * TILE_;
            #pragma unroll
            for (int j = 0; j < 4; j++) {
                uint32_t h0 = pack_half2(areg0[j].x, areg0[j].y);
                uint32_t h1 = pack_half2(areg0[j].z, areg0[j].w);
                STS64(ab + j * (32 * ROWB_), h0, h1);
            }
        }
        if (ck + 4 < NKC_) {
            #pragma unroll
            for (int j = 0; j < 4; j++)
                areg0[j] = *(const float4*)(srcA0 + (size_t)(32 * j) * D_ + (size_t)(ck + 4) * BK_);
        }
        if (ck + 3 < NKC_) {
            int nb = bufB + 3; if (nb >= NB_) nb -= NB_;
            #pragma unroll
            for (int j = 0; j < 2; j++)
                CP_ASYNC16(dstB[j] + nb * TILE_, srcB[j] + (size_t)(ck + 3) * 64);
        }
        CP_COMMIT();
        {
            const uint32_t abase = sb + bufA * TILE_;
            const uint32_t bbase = sb + bufB * TILE_;
            #pragma unroll
            for (int kk = 0; kk < 2; kk++) {
                uint32_t ah[4][4], bh[4][2];
                uint32_t ab = abase + a_off + kk * 32;
                uint32_t bb = bbase + b_off + kk * 32;
                #pragma unroll
                for (int mt = 0; mt < 4; mt++) LDSM4(ah[mt], ab + mt * (16 * ROWB_));
                #pragma unroll
                for (int nt = 0; nt < 4; nt++) LDSM2(bh[nt], bb + nt * (8 * ROWB_));
                #pragma unroll
                for (int mt = 0; mt < 4; mt++)
                    #pragma unroll
                    for (int nt = 0; nt < 4; nt++)
                        MMA_F32(acc[mt][nt], ah[mt], bh[nt]);
            }
        }

        // ===== odd sub-iter (ck+1): STS A(ck+3) from areg1; LDG A(ck+5) -> areg1 =====
        int bufA1 = bufA + 1; if (bufA1 >= NA_) bufA1 -= NA_;
        int bufB1 = bufB + 1; if (bufB1 >= NB_) bufB1 -= NB_;
        if (ck + 3 < NKC_) {
            int nb = bufA1 + 2; if (nb >= NA_) nb -= NA_;
            uint32_t ab = dstA0 + nb * TILE_;
            #pragma unroll
            for (int j = 0; j < 4; j++) {
                uint32_t h0 = pack_half2(areg1[j].x, areg1[j].y);
                uint32_t h1 = pack_half2(areg1[j].z, areg1[j].w);
                STS64(ab + j * (32 * ROWB_), h0, h1);
            }
        }
        if (ck + 5 < NKC_) {
            #pragma unroll
            for (int j = 0; j < 4; j++)
                areg1[j] = *(const float4*)(srcA0 + (size_t)(32 * j) * D_ + (size_t)(ck + 5) * BK_);
        }
        if (ck + 4 < NKC_) {
            int nb = bufB1 + 3; if (nb >= NB_) nb -= NB_;
            #pragma unroll
            for (int j = 0; j < 2; j++)
                CP_ASYNC16(dstB[j] + nb * TILE_, srcB[j] + (size_t)(ck + 4) * 64);
        }
        CP_COMMIT();
        {
            const uint32_t abase = sb + bufA1 * TILE_;
            const uint32_t bbase = sb + bufB1 * TILE_;
            #pragma unroll
            for (int kk = 0; kk < 2; kk++) {
                uint32_t ah[4][4], bh[4][2];
                uint32_t ab = abase + a_off + kk * 32;
                uint32_t bb = bbase + b_off + kk * 32;
                #pragma unroll
                for (int mt = 0; mt < 4; mt++) LDSM4(ah[mt], ab + mt * (16 * ROWB_));
                #pragma unroll
                for (int nt = 0; nt < 4; nt++) LDSM2(bh[nt], bb + nt * (8 * ROWB_));
                #pragma unroll
                for (int mt = 0; mt < 4; mt++)
                    #pragma unroll
                    for (int nt = 0; nt < 4; nt++)
                        MMA_F32(acc[mt][nt], ah[mt], bh[nt]);
            }
        }

        bufA += 2; if (bufA >= NA_) bufA -= NA_;
        bufB += 2; if (bufB >= NB_) bufB -= NB_;
    }

    // ---- epilogue: relu(acc + b1), chunk column-sums ----
    const float* sb1f = (const float*)(smem + SM_B1_);
    float csum[4][2];
    #pragma unroll
    for (int nt = 0; nt < 4; nt++) { csum[nt][0] = 0.f; csum[nt][1] = 0.f; }
    #pragma unroll
    for (int nt = 0; nt < 4; nt++) {
        int col = wn * 32 + nt * 8 + (lane & 3) * 2;
        float bv0 = sb1f[col], bv1 = sb1f[col + 1];
        #pragma unroll
        for (int mt = 0; mt < 4; mt++) {
            csum[nt][0] += fmaxf(acc[mt][nt][0] + bv0, 0.f) + fmaxf(acc[mt][nt][2] + bv0, 0.f);
            csum[nt][1] += fmaxf(acc[mt][nt][1] + bv1, 0.f) + fmaxf(acc[mt][nt][3] + bv1, 0.f);
        }
    }
    #pragma unroll
    for (int nt = 0; nt < 4; nt++)
        #pragma unroll
        for (int r = 0; r < 2; r++) {
            csum[nt][r] += __shfl_xor_sync(0xffffffffu, csum[nt][r], 4);
            csum[nt][r] += __shfl_xor_sync(0xffffffffu, csum[nt][r], 8);
            csum[nt][r] += __shfl_xor_sync(0xffffffffu, csum[nt][r], 16);
        }
    float* part = (float*)(smem + SM_PART_);    // [2][128]
    __syncthreads();
    if (lane < 4) {
        #pragma unroll
        for (int nt = 0; nt < 4; nt++) {
            int col = wn * 32 + nt * 8 + lane * 2;
            part[wm * BN_ + col] = csum[nt][0];
            part[wm * BN_ + col + 1] = csum[nt][1];
        }
    }
    __syncthreads();
    if (tid < BN_)
        g_hsum[(size_t)chunk * H_ + n0 + tid] = part[tid] + part[BN_ + tid];

    // ---- last-CTA-per-chunk: compute this chunk's 8 logits ----
    __threadfence();
    __shared__ int slast;
    if (tid == 0) slast = (atomicAdd(&g_cnt[chunk], 1) == 7) ? 1 : 0;
    __syncthreads();
    if (slast) {
        const float* hs = g_hsum + (size_t)chunk * H_;
        float lacc[E_];
        #pragma unroll
        for (int e = 0; e < E_; e++) lacc[e] = 0.f;
        for (int j = tid; j < H_; j += NTHR_) {
            float h = hs[j];
            float4 w0 = *(const float4*)(W2 + (size_t)j * E_);
            float4 w1 = *(const float4*)(W2 + (size_t)j * E_ + 4);
            lacc[0] += h * w0.x; lacc[1] += h * w0.y; lacc[2] += h * w0.z; lacc[3] += h * w0.w;
            lacc[4] += h * w1.x; lacc[5] += h * w1.y; lacc[6] += h * w1.z; lacc[7] += h * w1.w;
        }
        #pragma unroll
        for (int off = 16; off; off >>= 1)
            #pragma unroll
            for (int e = 0; e < E_; e++)
                lacc[e] += __shfl_down_sync(0xffffffffu, lacc[e], off);
        float* sred = part;                       // reuse [8][8]
        if (lane == 0) {
            #pragma unroll
            for (int e = 0; e < E_; e++) sred[wid * E_ + e] = lacc[e];
        }
        __syncthreads();
        if (tid < E_) {
            float s = 0.f;
            #pragma unroll
            for (int g = 0; g < 8; g++) s += sred[g * E_ + tid];
            g_clogits[chunk * E_ + tid] = s * (1.0f / (float)CHUNK_) + b2[tid];
        }
    }
}

// ---------------- per-chunk scan + one-hot fill (256 blocks, one per chunk) ----------------
__global__ __launch_bounds__(256)
void scan_fill(float* __restrict__ out, int out_size) {
    __shared__ float clog[32 * E_];
    __shared__ int   sidx;
    const int bc = blockIdx.x;          // global chunk 0..255
    const int b = bc >> 5, c = bc & 31;
    const int tid = threadIdx.x;

    clog[tid] = g_clogits[b * 32 * E_ + tid];
    __syncthreads();

    if (tid == 0) {
        g_cnt[bc] = 0;                  // reset for next graph replay
        int prev = 0;
        {
            float best = clog[0];
            #pragma unroll
            for (int e = 1; e < E_; e++)
                if (clog[e] > best) { best = clog[e]; prev = e; }
        }
        for (int cc = 1; cc <= c; cc++) {
            const float* l = clog + cc * E_;
            int ce = 0; float best = l[0];
            #pragma unroll
            for (int e = 1; e < E_; e++)
                if (l[e] > best) { best = l[e]; ce = e; }
            if (l[ce] - l[prev] > TAU_) prev = ce;
        }
        sidx = prev;
        if (out_size >= B_ * S_ * E_ + NCHUNK_)
            out[B_ * S_ * E_ + bc] = (float)prev;
    }
    __syncthreads();

    const int idx = sidx;
    float4* ob = (float4*)out + (size_t)bc * 256;
    int e0 = (tid & 1) * 4;
    float4 v;
    v.x = (e0 + 0 == idx) ? 1.0f : 0.0f;
    v.y = (e0 + 1 == idx) ? 1.0f : 0.0f;
    v.z = (e0 + 2 == idx) ? 1.0f : 0.0f;
    v.w = (e0 + 3 == idx) ? 1.0f : 0.0f;
    ob[tid] = v;
}

extern "C" void kernel_launch(void* const* d_in, const int* in_sizes, int n_in,
                              void* d_out, int out_size) {
    const float* x  = (const float*)d_in[0];
    const float* W1 = (const float*)d_in[1];
    const float* b1 = (const float*)d_in[2];
    const float* W2 = (const float*)d_in[3];
    const float* b2 = (const float*)d_in[4];
    float* out = (float*)d_out;

    cudaFuncSetAttribute(gemm1_mma, cudaFuncAttributeMaxDynamicSharedMemorySize, SMEM_TOTAL_);

    cvt_w1<<<dim3(H_ / 64, D_ / 64), 256>>>(W1);
    gemm1_mma<<<dim3(H_ / BN_, NCHUNK_), NTHR_, SMEM_TOTAL_>>>(x, b1, W2, b2);
    scan_fill<<<NCHUNK_, 256>>>(out, out_size);
}

// round 16
// speedup vs baseline: 1.0717x; 1.0717x over previous
#include <cuda_runtime.h>
#include <cuda_fp16.h>
#include <cstdint>

// ChunkStickyRouter on GB300 (sm_103a) — fp16 mma.sync GEMM1, 4+5-stage pipeline
// with barrier every 2nd k-chunk, fused x-cvt, last-CTA logits, per-chunk scan+fill.
// B=8, S=4096, D=2048, H=1024, E=8, CHUNK=128, TAU=0.7
// (R14 configuration — best measured: 417.8 us)

#define B_  8
#define S_  4096
#define D_  2048
#define H_  1024
#define E_  8
#define CHUNK_ 128
#define NCHUNK_ 256
#define TAU_ 0.7f

// GEMM1 tiling
#define BM_ 128
#define BN_ 128
#define BK_ 32
#define NKC_ (D_ / BK_)        // 64
#define NTHR_ 256
#define ROWB_ 80               // smem row stride (bytes): conflict-free LDSM
#define TILE_ (128 * ROWB_)            // 10240 B per fp16 tile
#define NA_ 4                          // A stages
#define NB_ 5                          // B stages
#define BOFF_ (NA_ * TILE_)            // 40960
#define SM_B1_   (BOFF_ + NB_ * TILE_) // 92160
#define SM_PART_ (SM_B1_ + 512)
#define SMEM_TOTAL_ (SM_PART_ + 1024)  // 93696  -> 2 CTAs/SM

__device__ __half g_w1t[(size_t)H_ * D_];         // W1^T as fp16, [n][k]
__device__ float  g_hsum[NCHUNK_ * H_];
__device__ float  g_clogits[NCHUNK_ * E_];
__device__ int    g_cnt[NCHUNK_];                 // per-chunk completion counters

// ---------------- PTX helpers ----------------
__device__ __forceinline__ uint32_t smem_to_u32(const void* p) {
    uint32_t a;
    asm("{ .reg .u64 t; cvta.to.shared.u64 t, %1; cvt.u32.u64 %0, t; }" : "=r"(a) : "l"(p));
    return a;
}
__device__ __forceinline__ uint32_t pack_half2(float x, float y) {
    uint32_t u;
    asm("cvt.rn.f16x2.f32 %0, %1, %2;" : "=r"(u) : "f"(y), "f"(x));
    return u;
}
#define CP_ASYNC16(dst, src) \
    asm volatile("cp.async.cg.shared.global [%0], [%1], 16;" :: "r"(dst), "l"(src))
#define CP_COMMIT() asm volatile("cp.async.commit_group;" ::: "memory")
#define CP_WAITG1() asm volatile("cp.async.wait_group 1;" ::: "memory")

#define LDSM4(r, a) \
    asm volatile("ldmatrix.sync.aligned.m8n8.x4.shared.b16 {%0,%1,%2,%3}, [%4];" \
        : "=r"((r)[0]), "=r"((r)[1]), "=r"((r)[2]), "=r"((r)[3]) : "r"(a))
#define LDSM2(r, a) \
    asm volatile("ldmatrix.sync.aligned.m8n8.x2.shared.b16 {%0,%1}, [%2];" \
        : "=r"((r)[0]), "=r"((r)[1]) : "r"(a))

#define MMA_F32(d, a, b) \
    asm volatile("mma.sync.aligned.m16n8k16.row.col.f32.f16.f16.f32 " \
        "{%0,%1,%2,%3}, {%4,%5,%6,%7}, {%8,%9}, {%0,%1,%2,%3};" \
        : "+f"((d)[0]), "+f"((d)[1]), "+f"((d)[2]), "+f"((d)[3]) \
        : "r"((a)[0]), "r"((a)[1]), "r"((a)[2]), "r"((a)[3]), "r"((b)[0]), "r"((b)[1]))

#define STS64(addr, v0, v1) \
    asm volatile("st.shared.v2.b32 [%0], {%1, %2};" :: "r"(addr), "r"(v0), "r"(v1))

// ---------------- prepass: W1 cvt (vectorized stores) + counter reset ----------------
__global__ void cvt_w1(const float* __restrict__ W1) {
    __shared__ float t[32][33];
    int n0 = blockIdx.x * 32, k0 = blockIdx.y * 32;
    int tx = threadIdx.x, ty = threadIdx.y;
    int tid = ty * 32 + tx;
    if (blockIdx.x == 0 && blockIdx.y == 0)
        g_cnt[tid] = 0;
    #pragma unroll
    for (int i = 0; i < 4; i++)
        t[ty + i * 8][tx] = W1[(size_t)(k0 + ty + i * 8) * H_ + n0 + tx];
    __syncthreads();
    // thread -> (n, 4 consecutive k); 8B store
    int n = tid >> 3, k4 = (tid & 7) * 4;
    uint2 h;
    h.x = pack_half2(t[k4 + 0][n], t[k4 + 1][n]);
    h.y = pack_half2(t[k4 + 2][n], t[k4 + 3][n]);
    *(uint2*)&g_w1t[(size_t)(n0 + n) * D_ + k0 + k4] = h;
}

// ---------------- GEMM1: relu(x@W1+b1), chunk column-sum, last-CTA logits ----------------
__global__ __launch_bounds__(NTHR_, 2)
void gemm1_mma(const float* __restrict__ x, const float* __restrict__ b1,
               const float* __restrict__ W2, const float* __restrict__ b2) {
    extern __shared__ __align__(1024) char smem[];
    const uint32_t sb = smem_to_u32(smem);
    const int tid = threadIdx.x;
    const int lane = tid & 31, wid = tid >> 5;      // 8 warps
    const int wm = wid & 1, wn = wid >> 1;          // 2(m) x 4(n), warp tile 64x32
    const int n0 = blockIdx.x * BN_;
    const int chunk = blockIdx.y;
    const int m0 = chunk * BM_;

    if (tid < BN_) ((float*)(smem + SM_B1_))[tid] = b1[n0 + tid];

    // ---- A (x fp32, LDG prefetch): thread covers 4 float4 chunks ----
    const int a_row0 = tid >> 3;            // +32*j
    const int a_k4   = tid & 7;
    const float* srcA0 = x + (size_t)(m0 + a_row0) * D_ + a_k4 * 4;
    const uint32_t dstA0 = sb + a_row0 * ROWB_ + a_k4 * 8;   // fp16: 8B per float4

    // ---- B (w1t fp16, cp.async): 2 chunks of 16B per thread ----
    const char* srcB[2]; uint32_t dstB[2];
    #pragma unroll
    for (int j = 0; j < 2; j++) {
        int q = tid + j * NTHR_;               // 0..511
        int row = q >> 2, k16 = q & 3;
        srcB[j] = (const char*)(g_w1t + (size_t)(n0 + row) * D_ + k16 * 8);
        dstB[j] = sb + BOFF_ + row * ROWB_ + k16 * 16;
    }

    const uint32_t a_off = (uint32_t)((wm * 64 + (lane & 15)) * ROWB_ + (lane >> 4) * 16);
    const uint32_t b_off = (uint32_t)(BOFF_ + (wn * 32 + (lane & 7)) * ROWB_ + ((lane >> 3) & 1) * 16);

    float acc[4][4][4];
    #pragma unroll
    for (int a = 0; a < 4; a++)
        #pragma unroll
        for (int b = 0; b < 4; b++)
            #pragma unroll
            for (int c = 0; c < 4; c++) acc[a][b][c] = 0.f;

    float4 areg[4];

    // ---- prologue: A0,A1 -> smem; A2 -> regs; B0,B1,B2 cp.async ----
    #pragma unroll
    for (int s = 0; s < 2; s++) {
        #pragma unroll
        for (int j = 0; j < 4; j++)
            areg[j] = *(const float4*)(srcA0 + (size_t)(32 * j) * D_ + s * BK_);
        #pragma unroll
        for (int j = 0; j < 4; j++) {
            uint32_t h0 = pack_half2(areg[j].x, areg[j].y);
            uint32_t h1 = pack_half2(areg[j].z, areg[j].w);
            STS64(dstA0 + s * TILE_ + j * (32 * ROWB_), h0, h1);
        }
    }
    #pragma unroll
    for (int j = 0; j < 4; j++)
        areg[j] = *(const float4*)(srcA0 + (size_t)(32 * j) * D_ + 2 * BK_);
    #pragma unroll
    for (int s = 0; s < 3; s++) {
        #pragma unroll
        for (int j = 0; j < 2; j++)
            CP_ASYNC16(dstB[j] + s * TILE_, srcB[j] + s * 64);
        CP_COMMIT();
    }

    int bufA = 0, bufB = 0;                 // ck % 4, ck % 5
    for (int ck = 0; ck < NKC_; ck++) {
        if ((ck & 1) == 0) {
            CP_WAITG1();
            __syncthreads();
        }

        // stage A(ck+2) regs -> bufA[(ck+2)%4] ; prefetch A(ck+3)
        if (ck + 2 < NKC_) {
            int nb = bufA + 2; if (nb >= NA_) nb -= NA_;
            uint32_t ab = dstA0 + nb * TILE_;
            #pragma unroll
            for (int j = 0; j < 4; j++) {
                uint32_t h0 = pack_half2(areg[j].x, areg[j].y);
                uint32_t h1 = pack_half2(areg[j].z, areg[j].w);
                STS64(ab + j * (32 * ROWB_), h0, h1);
            }
        }
        if (ck + 3 < NKC_) {
            #pragma unroll
            for (int j = 0; j < 4; j++)
                areg[j] = *(const float4*)(srcA0 + (size_t)(32 * j) * D_ + (size_t)(ck + 3) * BK_);
            // B(ck+3) -> bufB[(ck+3)%5]
            int nb = bufB + 3; if (nb >= NB_) nb -= NB_;
            uint32_t sbase = nb * TILE_;
            #pragma unroll
            for (int j = 0; j < 2; j++)
                CP_ASYNC16(dstB[j] + sbase, srcB[j] + (size_t)(ck + 3) * 64);
        }
        CP_COMMIT();   // unconditional: keeps group counting uniform

        const uint32_t abase = sb + bufA * TILE_;
        const uint32_t bbase = sb + bufB * TILE_;   // b_off already includes BOFF_
        #pragma unroll
        for (int kk = 0; kk < 2; kk++) {
            uint32_t ah[4][4], bh[4][2];
            uint32_t ab = abase + a_off + kk * 32;
            uint32_t bb = bbase + b_off + kk * 32;
            #pragma unroll
            for (int mt = 0; mt < 4; mt++) LDSM4(ah[mt], ab + mt * (16 * ROWB_));
            #pragma unroll
            for (int nt = 0; nt < 4; nt++) LDSM2(bh[nt], bb + nt * (8 * ROWB_));
            #pragma unroll
            for (int mt = 0; mt < 4; mt++)
                #pragma unroll
                for (int nt = 0; nt < 4; nt++)
                    MMA_F32(acc[mt][nt], ah[mt], bh[nt]);
        }
        bufA++; if (bufA >= NA_) bufA = 0;
        bufB++; if (bufB >= NB_) bufB = 0;
    }

    // ---- epilogue: relu(acc + b1), chunk column-sums ----
    const float* sb1f = (const float*)(smem + SM_B1_);
    float csum[4][2];
    #pragma unroll
    for (int nt = 0; nt < 4; nt++) { csum[nt][0] = 0.f; csum[nt][1] = 0.f; }
    #pragma unroll
    for (int nt = 0; nt < 4; nt++) {
        int col = wn * 32 + nt * 8 + (lane & 3) * 2;
        float bv0 = sb1f[col], bv1 = sb1f[col + 1];
        #pragma unroll
        for (int mt = 0; mt < 4; mt++) {
            csum[nt][0] += fmaxf(acc[mt][nt][0] + bv0, 0.f) + fmaxf(acc[mt][nt][2] + bv0, 0.f);
            csum[nt][1] += fmaxf(acc[mt][nt][1] + bv1, 0.f) + fmaxf(acc[mt][nt][3] + bv1, 0.f);
        }
    }
    #pragma unroll
    for (int nt = 0; nt < 4; nt++)
        #pragma unroll
        for (int r = 0; r < 2; r++) {
            csum[nt][r] += __shfl_xor_sync(0xffffffffu, csum[nt][r], 4);
            csum[nt][r] += __shfl_xor_sync(0xffffffffu, csum[nt][r], 8);
            csum[nt][r] += __shfl_xor_sync(0xffffffffu, csum[nt][r], 16);
        }
    float* part = (float*)(smem + SM_PART_);    // [2][128]
    __syncthreads();
    if (lane < 4) {
        #pragma unroll
        for (int nt = 0; nt < 4; nt++) {
            int col = wn * 32 + nt * 8 + lane * 2;
            part[wm * BN_ + col] = csum[nt][0];
            part[wm * BN_ + col + 1] = csum[nt][1];
        }
    }
    __syncthreads();
    if (tid < BN_)
        g_hsum[(size_t)chunk * H_ + n0 + tid] = part[tid] + part[BN_ + tid];

    // ---- last-CTA-per-chunk: compute this chunk's 8 logits ----
    __threadfence();
    __shared__ int slast;
    if (tid == 0) slast = (atomicAdd(&g_cnt[chunk], 1) == 7) ? 1 : 0;
    __syncthreads();
    if (slast) {
        const float* hs = g_hsum + (size_t)chunk * H_;
        float lacc[E_];
        #pragma unroll
        for (int e = 0; e < E_; e++) lacc[e] = 0.f;
        for (int j = tid; j < H_; j += NTHR_) {
            float h = hs[j];
            float4 w0 = *(const float4*)(W2 + (size_t)j * E_);
            float4 w1 = *(const float4*)(W2 + (size_t)j * E_ + 4);
            lacc[0] += h * w0.x; lacc[1] += h * w0.y; lacc[2] += h * w0.z; lacc[3] += h * w0.w;
            lacc[4] += h * w1.x; lacc[5] += h * w1.y; lacc[6] += h * w1.z; lacc[7] += h * w1.w;
        }
        #pragma unroll
        for (int off = 16; off; off >>= 1)
            #pragma unroll
            for (int e = 0; e < E_; e++)
                lacc[e] += __shfl_down_sync(0xffffffffu, lacc[e], off);
        float* sred = part;                       // reuse [8][8]
        if (lane == 0) {
            #pragma unroll
            for (int e = 0; e < E_; e++) sred[wid * E_ + e] = lacc[e];
        }
        __syncthreads();
        if (tid < E_) {
            float s = 0.f;
            #pragma unroll
            for (int g = 0; g < 8; g++) s += sred[g * E_ + tid];
            g_clogits[chunk * E_ + tid] = s * (1.0f / (float)CHUNK_) + b2[tid];
        }
    }
}

// ---------------- per-chunk scan + one-hot fill (256 blocks, one per chunk) ----------------
__global__ __launch_bounds__(256)
void scan_fill(float* __restrict__ out, int out_size) {
    __shared__ float clog[32 * E_];
    __shared__ int   sidx;
    const int bc = blockIdx.x;          // global chunk 0..255
    const int b = bc >> 5, c = bc & 31;
    const int tid = threadIdx.x;

    clog[tid] = g_clogits[b * 32 * E_ + tid];
    __syncthreads();

    if (tid == 0) {
        int prev = 0;
        {
            float best = clog[0];
            #pragma unroll
            for (int e = 1; e < E_; e++)
                if (clog[e] > best) { best = clog[e]; prev = e; }
        }
        for (int cc = 1; cc <= c; cc++) {
            const float* l = clog + cc * E_;
            int ce = 0; float best = l[0];
            #pragma unroll
            for (int e = 1; e < E_; e++)
                if (l[e] > best) { best = l[e]; ce = e; }
            if (l[ce] - l[prev] > TAU_) prev = ce;
        }
        sidx = prev;
        if (out_size >= B_ * S_ * E_ + NCHUNK_)
            out[B_ * S_ * E_ + bc] = (float)prev;
    }
    __syncthreads();

    const int idx = sidx;
    float4* ob = (float4*)out + (size_t)bc * 256;
    int e0 = (tid & 1) * 4;
    float4 v;
    v.x = (e0 + 0 == idx) ? 1.0f : 0.0f;
    v.y = (e0 + 1 == idx) ? 1.0f : 0.0f;
    v.z = (e0 + 2 == idx) ? 1.0f : 0.0f;
    v.w = (e0 + 3 == idx) ? 1.0f : 0.0f;
    ob[tid] = v;
}

extern "C" void kernel_launch(void* const* d_in, const int* in_sizes, int n_in,
                              void* d_out, int out_size) {
    const float* x  = (const float*)d_in[0];
    const float* W1 = (const float*)d_in[1];
    const float* b1 = (const float*)d_in[2];
    const float* W2 = (const float*)d_in[3];
    const float* b2 = (const float*)d_in[4];
    float* out = (float*)d_out;

    cudaFuncSetAttribute(gemm1_mma, cudaFuncAttributeMaxDynamicSharedMemorySize, SMEM_TOTAL_);

    cvt_w1<<<dim3(H_ / 32, D_ / 32), dim3(32, 8)>>>(W1);
    gemm1_mma<<<dim3(H_ / BN_, NCHUNK_), NTHR_, SMEM_TOTAL_>>>(x, b1, W2, b2);
    scan_fill<<<NCHUNK_, 256>>>(out, out_size);
}

// round 17
// speedup vs baseline: 1.2273x; 1.1452x over previous
#include <cuda_runtime.h>
#include <cuda_fp16.h>
#include <cstdint>

// ChunkStickyRouter on GB300 (sm_103a) — fp16 mma.sync GEMM1 (BM128 x BN256,
// 512 thr, 1 CTA/SM), barrier every 2nd k-chunk, fused x-cvt, last-CTA logits,
// per-chunk scan+fill. B=8, S=4096, D=2048, H=1024, E=8, CHUNK=128, TAU=0.7

#define B_  8
#define S_  4096
#define D_  2048
#define H_  1024
#define E_  8
#define CHUNK_ 128
#define NCHUNK_ 256
#define TAU_ 0.7f

// GEMM1 tiling
#define BM_ 128
#define BN_ 256
#define BK_ 32
#define NKC_ (D_ / BK_)        // 64
#define NTHR_ 512
#define ROWB_ 80               // smem row stride (bytes): conflict-free LDSM
#define ATILE_ (128 * ROWB_)           // 10240 B per A fp16 tile
#define BTILE_ (256 * ROWB_)           // 20480 B per B fp16 tile
#define NA_ 4                          // A stages
#define NB_ 5                          // B stages
#define BOFF_ (NA_ * ATILE_)           // 40960
#define SM_B1_   (BOFF_ + NB_ * BTILE_) // 143360
#define SM_PART_ (SM_B1_ + 1024)        // b1: 256 floats
#define SMEM_TOTAL_ (SM_PART_ + 2048)   // 146432 -> 1 CTA/SM (16 warps)

__device__ __half g_w1t[(size_t)H_ * D_];         // W1^T as fp16, [n][k]
__device__ float  g_hsum[NCHUNK_ * H_];
__device__ float  g_clogits[NCHUNK_ * E_];
__device__ int    g_cnt[NCHUNK_];                 // per-chunk completion counters

// ---------------- PTX helpers ----------------
__device__ __forceinline__ uint32_t smem_to_u32(const void* p) {
    uint32_t a;
    asm("{ .reg .u64 t; cvta.to.shared.u64 t, %1; cvt.u32.u64 %0, t; }" : "=r"(a) : "l"(p));
    return a;
}
__device__ __forceinline__ uint32_t pack_half2(float x, float y) {
    uint32_t u;
    asm("cvt.rn.f16x2.f32 %0, %1, %2;" : "=r"(u) : "f"(y), "f"(x));
    return u;
}
#define CP_ASYNC16(dst, src) \
    asm volatile("cp.async.cg.shared.global [%0], [%1], 16;" :: "r"(dst), "l"(src))
#define CP_COMMIT() asm volatile("cp.async.commit_group;" ::: "memory")
#define CP_WAITG1() asm volatile("cp.async.wait_group 1;" ::: "memory")

#define LDSM4(r, a) \
    asm volatile("ldmatrix.sync.aligned.m8n8.x4.shared.b16 {%0,%1,%2,%3}, [%4];" \
        : "=r"((r)[0]), "=r"((r)[1]), "=r"((r)[2]), "=r"((r)[3]) : "r"(a))
#define LDSM2(r, a) \
    asm volatile("ldmatrix.sync.aligned.m8n8.x2.shared.b16 {%0,%1}, [%2];" \
        : "=r"((r)[0]), "=r"((r)[1]) : "r"(a))

#define MMA_F32(d, a, b) \
    asm volatile("mma.sync.aligned.m16n8k16.row.col.f32.f16.f16.f32 " \
        "{%0,%1,%2,%3}, {%4,%5,%6,%7}, {%8,%9}, {%0,%1,%2,%3};" \
        : "+f"((d)[0]), "+f"((d)[1]), "+f"((d)[2]), "+f"((d)[3]) \
        : "r"((a)[0]), "r"((a)[1]), "r"((a)[2]), "r"((a)[3]), "r"((b)[0]), "r"((b)[1]))

#define STS64(addr, v0, v1) \
    asm volatile("st.shared.v2.b32 [%0], {%1, %2};" :: "r"(addr), "r"(v0), "r"(v1))

// ---------------- prepass: W1 cvt (vectorized stores) + counter reset ----------------
__global__ void cvt_w1(const float* __restrict__ W1) {
    __shared__ float t[32][33];
    int n0 = blockIdx.x * 32, k0 = blockIdx.y * 32;
    int tx = threadIdx.x, ty = threadIdx.y;
    int tid = ty * 32 + tx;
    if (blockIdx.x == 0 && blockIdx.y == 0)
        g_cnt[tid] = 0;
    #pragma unroll
    for (int i = 0; i < 4; i++)
        t[ty + i * 8][tx] = W1[(size_t)(k0 + ty + i * 8) * H_ + n0 + tx];
    __syncthreads();
    // thread -> (n, 4 consecutive k); 8B store
    int n = tid >> 3, k4 = (tid & 7) * 4;
    uint2 h;
    h.x = pack_half2(t[k4 + 0][n], t[k4 + 1][n]);
    h.y = pack_half2(t[k4 + 2][n], t[k4 + 3][n]);
    *(uint2*)&g_w1t[(size_t)(n0 + n) * D_ + k0 + k4] = h;
}

// ---------------- GEMM1: relu(x@W1+b1), chunk column-sum, last-CTA logits ----------------
__global__ __launch_bounds__(NTHR_, 1)
void gemm1_mma(const float* __restrict__ x, const float* __restrict__ b1,
               const float* __restrict__ W2, const float* __restrict__ b2) {
    extern __shared__ __align__(1024) char smem[];
    const uint32_t sb = smem_to_u32(smem);
    const int tid = threadIdx.x;
    const int lane = tid & 31, wid = tid >> 5;      // 16 warps
    const int wm = wid & 1, wn = wid >> 1;          // 2(m) x 8(n), warp tile 64x32
    const int n0 = blockIdx.x * BN_;
    const int chunk = blockIdx.y;
    const int m0 = chunk * BM_;

    if (tid < BN_) ((float*)(smem + SM_B1_))[tid] = b1[n0 + tid];

    // ---- A (x fp32, LDG prefetch): thread covers 2 float4 chunks ----
    // q = tid + j*512, j=0..1 : row = q>>3 (0..127), k4 = q&7
    const int a_row0 = tid >> 3;            // +64*j
    const int a_k4   = tid & 7;
    const float* srcA0 = x + (size_t)(m0 + a_row0) * D_ + a_k4 * 4;
    const uint32_t dstA0 = sb + a_row0 * ROWB_ + a_k4 * 8;   // fp16: 8B per float4

    // ---- B (w1t fp16, cp.async): 2 chunks of 16B per thread ----
    const char* srcB[2]; uint32_t dstB[2];
    #pragma unroll
    for (int j = 0; j < 2; j++) {
        int q = tid + j * NTHR_;               // 0..1023
        int row = q >> 2, k16 = q & 3;         // row 0..255
        srcB[j] = (const char*)(g_w1t + (size_t)(n0 + row) * D_ + k16 * 8);
        dstB[j] = sb + BOFF_ + row * ROWB_ + k16 * 16;
    }

    const uint32_t a_off = (uint32_t)((wm * 64 + (lane & 15)) * ROWB_ + (lane >> 4) * 16);
    const uint32_t b_off = (uint32_t)(BOFF_ + (wn * 32 + (lane & 7)) * ROWB_ + ((lane >> 3) & 1) * 16);

    float acc[4][4][4];
    #pragma unroll
    for (int a = 0; a < 4; a++)
        #pragma unroll
        for (int b = 0; b < 4; b++)
            #pragma unroll
            for (int c = 0; c < 4; c++) acc[a][b][c] = 0.f;

    float4 areg[2];

    // ---- prologue: A0,A1 -> smem; A2 -> regs; B0,B1,B2 cp.async ----
    #pragma unroll
    for (int s = 0; s < 2; s++) {
        #pragma unroll
        for (int j = 0; j < 2; j++)
            areg[j] = *(const float4*)(srcA0 + (size_t)(64 * j) * D_ + s * BK_);
        #pragma unroll
        for (int j = 0; j < 2; j++) {
            uint32_t h0 = pack_half2(areg[j].x, areg[j].y);
            uint32_t h1 = pack_half2(areg[j].z, areg[j].w);
            STS64(dstA0 + s * ATILE_ + j * (64 * ROWB_), h0, h1);
        }
    }
    #pragma unroll
    for (int j = 0; j < 2; j++)
        areg[j] = *(const float4*)(srcA0 + (size_t)(64 * j) * D_ + 2 * BK_);
    #pragma unroll
    for (int s = 0; s < 3; s++) {
        #pragma unroll
        for (int j = 0; j < 2; j++)
            CP_ASYNC16(dstB[j] + s * BTILE_, srcB[j] + s * 64);
        CP_COMMIT();
    }

    int bufA = 0, bufB = 0;                 // ck % 4, ck % 5
    for (int ck = 0; ck < NKC_; ck++) {
        if ((ck & 1) == 0) {
            CP_WAITG1();
            __syncthreads();
        }

        // stage A(ck+2) regs -> bufA[(ck+2)%4] ; prefetch A(ck+3)
        if (ck + 2 < NKC_) {
            int nb = bufA + 2; if (nb >= NA_) nb -= NA_;
            uint32_t ab = dstA0 + nb * ATILE_;
            #pragma unroll
            for (int j = 0; j < 2; j++) {
                uint32_t h0 = pack_half2(areg[j].x, areg[j].y);
                uint32_t h1 = pack_half2(areg[j].z, areg[j].w);
                STS64(ab + j * (64 * ROWB_), h0, h1);
            }
        }
        if (ck + 3 < NKC_) {
            #pragma unroll
            for (int j = 0; j < 2; j++)
                areg[j] = *(const float4*)(srcA0 + (size_t)(64 * j) * D_ + (size_t)(ck + 3) * BK_);
            // B(ck+3) -> bufB[(ck+3)%5]
            int nb = bufB + 3; if (nb >= NB_) nb -= NB_;
            uint32_t sbase = nb * BTILE_;
            #pragma unroll
            for (int j = 0; j < 2; j++)
                CP_ASYNC16(dstB[j] + sbase, srcB[j] + (size_t)(ck + 3) * 64);
        }
        CP_COMMIT();   // unconditional: keeps group counting uniform

        const uint32_t abase = sb + bufA * ATILE_;
        const uint32_t bbase = sb + bufB * BTILE_;   // b_off already includes BOFF_
        #pragma unroll
        for (int kk = 0; kk < 2; kk++) {
            uint32_t ah[4][4], bh[4][2];
            uint32_t ab = abase + a_off + kk * 32;
            uint32_t bb = bbase + b_off + kk * 32;
            #pragma unroll
            for (int mt = 0; mt < 4; mt++) LDSM4(ah[mt], ab + mt * (16 * ROWB_));
            #pragma unroll
            for (int nt = 0; nt < 4; nt++) LDSM2(bh[nt], bb + nt * (8 * ROWB_));
            #pragma unroll
            for (int mt = 0; mt < 4; mt++)
                #pragma unroll
                for (int nt = 0; nt < 4; nt++)
                    MMA_F32(acc[mt][nt], ah[mt], bh[nt]);
        }
        bufA++; if (bufA >= NA_) bufA = 0;
        bufB++; if (bufB >= NB_) bufB = 0;
    }

    // ---- epilogue: relu(acc + b1), chunk column-sums ----
    const float* sb1f = (const float*)(smem + SM_B1_);
    float csum[4][2];
    #pragma unroll
    for (int nt = 0; nt < 4; nt++) { csum[nt][0] = 0.f; csum[nt][1] = 0.f; }
    #pragma unroll
    for (int nt = 0; nt < 4; nt++) {
        int col = wn * 32 + nt * 8 + (lane & 3) * 2;
        float bv0 = sb1f[col], bv1 = sb1f[col + 1];
        #pragma unroll
        for (int mt = 0; mt < 4; mt++) {
            csum[nt][0] += fmaxf(acc[mt][nt][0] + bv0, 0.f) + fmaxf(acc[mt][nt][2] + bv0, 0.f);
            csum[nt][1] += fmaxf(acc[mt][nt][1] + bv1, 0.f) + fmaxf(acc[mt][nt][3] + bv1, 0.f);
        }
    }
    #pragma unroll
    for (int nt = 0; nt < 4; nt++)
        #pragma unroll
        for (int r = 0; r < 2; r++) {
            csum[nt][r] += __shfl_xor_sync(0xffffffffu, csum[nt][r], 4);
            csum[nt][r] += __shfl_xor_sync(0xffffffffu, csum[nt][r], 8);
            csum[nt][r] += __shfl_xor_sync(0xffffffffu, csum[nt][r], 16);
        }
    float* part = (float*)(smem + SM_PART_);    // [2][256]
    __syncthreads();
    if (lane < 4) {
        #pragma unroll
        for (int nt = 0; nt < 4; nt++) {
            int col = wn * 32 + nt * 8 + lane * 2;
            part[wm * BN_ + col] = csum[nt][0];
            part[wm * BN_ + col + 1] = csum[nt][1];
        }
    }
    __syncthreads();
    if (tid < BN_)
        g_hsum[(size_t)chunk * H_ + n0 + tid] = part[tid] + part[BN_ + tid];

    // ---- last-CTA-per-chunk (4 CTAs/chunk): compute this chunk's 8 logits ----
    __threadfence();
    __shared__ int slast;
    if (tid == 0) slast = (atomicAdd(&g_cnt[chunk], 1) == 3) ? 1 : 0;
    __syncthreads();
    if (slast) {
        const float* hs = g_hsum + (size_t)chunk * H_;
        float lacc[E_];
        #pragma unroll
        for (int e = 0; e < E_; e++) lacc[e] = 0.f;
        for (int j = tid; j < H_; j += NTHR_) {
            float h = hs[j];
            float4 w0 = *(const float4*)(W2 + (size_t)j * E_);
            float4 w1 = *(const float4*)(W2 + (size_t)j * E_ + 4);
            lacc[0] += h * w0.x; lacc[1] += h * w0.y; lacc[2] += h * w0.z; lacc[3] += h * w0.w;
            lacc[4] += h * w1.x; lacc[5] += h * w1.y; lacc[6] += h * w1.z; lacc[7] += h * w1.w;
        }
        #pragma unroll
        for (int off = 16; off; off >>= 1)
            #pragma unroll
            for (int e = 0; e < E_; e++)
                lacc[e] += __shfl_down_sync(0xffffffffu, lacc[e], off);
        float* sred = part;                       // reuse [16][8]
        if (lane == 0) {
            #pragma unroll
            for (int e = 0; e < E_; e++) sred[wid * E_ + e] = lacc[e];
        }
        __syncthreads();
        if (tid < E_) {
            float s = 0.f;
            #pragma unroll
            for (int g = 0; g < 16; g++) s += sred[g * E_ + tid];
            g_clogits[chunk * E_ + tid] = s * (1.0f / (float)CHUNK_) + b2[tid];
        }
    }
}

// ---------------- per-chunk scan + one-hot fill (256 blocks, one per chunk) ----------------
__global__ __launch_bounds__(256)
void scan_fill(float* __restrict__ out, int out_size) {
    __shared__ float clog[32 * E_];
    __shared__ int   sidx;
    const int bc = blockIdx.x;          // global chunk 0..255
    const int b = bc >> 5, c = bc & 31;
    const int tid = threadIdx.x;

    clog[tid] = g_clogits[b * 32 * E_ + tid];
    __syncthreads();

    if (tid == 0) {
        int prev = 0;
        {
            float best = clog[0];
            #pragma unroll
            for (int e = 1; e < E_; e++)
                if (clog[e] > best) { best = clog[e]; prev = e; }
        }
        for (int cc = 1; cc <= c; cc++) {
            const float* l = clog + cc * E_;
            int ce = 0; float best = l[0];
            #pragma unroll
            for (int e = 1; e < E_; e++)
                if (l[e] > best) { best = l[e]; ce = e; }
            if (l[ce] - l[prev] > TAU_) prev = ce;
        }
        sidx = prev;
        if (out_size >= B_ * S_ * E_ + NCHUNK_)
            out[B_ * S_ * E_ + bc] = (float)prev;
    }
    __syncthreads();

    const int idx = sidx;
    float4* ob = (float4*)out + (size_t)bc * 256;
    int e0 = (tid & 1) * 4;
    float4 v;
    v.x = (e0 + 0 == idx) ? 1.0f : 0.0f;
    v.y = (e0 + 1 == idx) ? 1.0f : 0.0f;
    v.z = (e0 + 2 == idx) ? 1.0f : 0.0f;
    v.w = (e0 + 3 == idx) ? 1.0f : 0.0f;
    ob[tid] = v;
}

extern "C" void kernel_launch(void* const* d_in, const int* in_sizes, int n_in,
                              void* d_out, int out_size) {
    const float* x  = (const float*)d_in[0];
    const float* W1 = (const float*)d_in[1];
    const float* b1 = (const float*)d_in[2];
    const float* W2 = (const float*)d_in[3];
    const float* b2 = (const float*)d_in[4];
    float* out = (float*)d_out;

    cudaFuncSetAttribute(gemm1_mma, cudaFuncAttributeMaxDynamicSharedMemorySize, SMEM_TOTAL_);

    cvt_w1<<<dim3(H_ / 32, D_ / 32), dim3(32, 8)>>>(W1);
    gemm1_mma<<<dim3(H_ / BN_, NCHUNK_), NTHR_, SMEM_TOTAL_>>>(x, b1, W2, b2);
    scan_fill<<<NCHUNK_, 256>>>(out, out_size);
}